// round 3
// baseline (speedup 1.0000x reference)
#include <cuda_runtime.h>

// LocalVariation: out[b, k, y, x] = x[b,0,y,x] - x_padded[b,0,y+i,x+j]
// for the 24 off-center (i,j) in a 5x5 window, replicate padding.
//
// Shapes: x = [16, 1, 512, 512] fp32, out = [16, 24, 512, 512] fp32.
// Strategy: write-bandwidth-bound kernel. SMEM halo tile, float4 stores.

#define H 512
#define W 512
#define NB 16
#define KCH 24          // 5*5 - 1
#define TILE_W 128      // 32 threads * 4 px
#define TILE_H 8
#define SM_ROWS (TILE_H + 4)
#define SM_COLS (TILE_W + 4)
// Pad row stride to a multiple of 4 floats (16B) so per-thread 8-float row
// reads vectorize to LDS.128. 132 floats = 528 B = 33*16 ✓, and 132 >= 128+4.
#define SM_STRIDE 132
#define SM_ELEMS (SM_ROWS * SM_COLS)   // 1584

__global__ __launch_bounds__(256, 4)
void local_variation_kernel(const float* __restrict__ x, float* __restrict__ out) {
    __shared__ float tile[SM_ROWS][SM_STRIDE];

    const int b   = blockIdx.z;
    const int ty0 = blockIdx.y * TILE_H;
    const int tx0 = blockIdx.x * TILE_W;

    const float* __restrict__ xb = x + (size_t)b * H * W;

    // ---- cooperative halo fill with replicate-pad clamping ----
    // 1584 elements / 256 threads -> 7 fixed iterations (last guarded).
    // Fully unrolled so ptxas front-batches the LDGs (high MLP_p1).
    const int t = threadIdx.y * 32 + threadIdx.x;
    #pragma unroll
    for (int it = 0; it < 7; it++) {
        const int idx = t + it * 256;
        if (idx < SM_ELEMS) {
            const int r = idx / SM_COLS;
            const int c = idx - r * SM_COLS;
            const int gy = min(max(ty0 + r - 2, 0), H - 1);
            const int gx = min(max(tx0 + c - 2, 0), W - 1);
            tile[r][c] = __ldg(&xb[gy * W + gx]);
        }
    }
    __syncthreads();

    // ---- per-thread: 4 consecutive output pixels ----
    const int ry = threadIdx.y;           // row within tile
    const int cx = threadIdx.x * 4;       // leftmost of 4 px (smem col offset)

    // Load the 5x8 register window: rows ry..ry+4, cols cx..cx+7.
    // Each row = two aligned LDS.128 (16B apart), conflict-free.
    float rw[5][8];
    #pragma unroll
    for (int i = 0; i < 5; i++) {
        const float4 a = *(const float4*)&tile[ry + i][cx];
        const float4 q = *(const float4*)&tile[ry + i][cx + 4];
        rw[i][0] = a.x; rw[i][1] = a.y; rw[i][2] = a.z; rw[i][3] = a.w;
        rw[i][4] = q.x; rw[i][5] = q.y; rw[i][6] = q.z; rw[i][7] = q.w;
    }

    const float c0 = rw[2][2], c1 = rw[2][3], c2 = rw[2][4], c3 = rw[2][5];

    const int y = ty0 + ry;
    float* __restrict__ ob =
        out + ((size_t)b * KCH) * (size_t)(H * W) + (size_t)y * W + (tx0 + cx);

    int k = 0;
    #pragma unroll
    for (int i = 0; i < 5; i++) {
        #pragma unroll
        for (int j = 0; j < 5; j++) {
            if (i == 2 && j == 2) continue;
            float4 v;
            v.x = c0 - rw[i][j];
            v.y = c1 - rw[i][j + 1];
            v.z = c2 - rw[i][j + 2];
            v.w = c3 - rw[i][j + 3];
            *(float4*)(ob + (size_t)k * (H * W)) = v;
            k++;
        }
    }
}

extern "C" void kernel_launch(void* const* d_in, const int* in_sizes, int n_in,
                              void* d_out, int out_size) {
    const float* x = (const float*)d_in[0];
    float* out = (float*)d_out;

    dim3 block(32, 8, 1);
    dim3 grid(W / TILE_W, H / TILE_H, NB);   // (4, 64, 16)
    local_variation_kernel<<<grid, block>>>(x, out);
}

// round 5
// speedup vs baseline: 1.1101x; 1.1101x over previous
#include <cuda_runtime.h>

// LocalVariation: out[b, k, y, x] = x[b,0,y,x] - x_padded[b,0,y+i,x+j]
// for the 24 off-center (i,j) in a 5x5 window, replicate padding.
//
// Shapes: x = [16, 1, 512, 512] fp32, out = [16, 24, 512, 512] fp32.
// R4 (resubmit, infra timeout): row-streamed window (load smem row i inside
// the channel loop) to cut live registers 62 -> ~40 and raise occupancy
// 4 -> 6 CTA/SM; streaming stores (__stcs) since the 403MB output is
// write-once.

#define H 512
#define W 512
#define NB 16
#define KCH 24          // 5*5 - 1
#define TILE_W 128      // 32 threads * 4 px
#define TILE_H 8
#define SM_ROWS (TILE_H + 4)
#define SM_COLS (TILE_W + 4)
// Row stride padded to multiple of 4 floats (16B): per-thread 8-float row
// reads compile to two aligned, conflict-free LDS.128.
#define SM_STRIDE 132
#define SM_ELEMS (SM_ROWS * SM_COLS)   // 1584

__global__ __launch_bounds__(256, 6)
void local_variation_kernel(const float* __restrict__ x, float* __restrict__ out) {
    __shared__ float tile[SM_ROWS][SM_STRIDE];

    const int b   = blockIdx.z;
    const int ty0 = blockIdx.y * TILE_H;
    const int tx0 = blockIdx.x * TILE_W;

    const float* __restrict__ xb = x + (size_t)b * H * W;

    // ---- cooperative halo fill with replicate-pad clamping ----
    // 1584 elements / 256 threads -> 7 unrolled iterations (last guarded),
    // front-batching the LDGs.
    const int t = threadIdx.y * 32 + threadIdx.x;
    #pragma unroll
    for (int it = 0; it < 7; it++) {
        const int idx = t + it * 256;
        if (idx < SM_ELEMS) {
            const int r = idx / SM_COLS;
            const int c = idx - r * SM_COLS;
            const int gy = min(max(ty0 + r - 2, 0), H - 1);
            const int gx = min(max(tx0 + c - 2, 0), W - 1);
            tile[r][c] = __ldg(&xb[gy * W + gx]);
        }
    }
    __syncthreads();

    // ---- per-thread: 4 consecutive output pixels ----
    const int ry = threadIdx.y;           // row within tile
    const int cx = threadIdx.x * 4;       // leftmost of 4 px (smem col offset)

    // Center pixels (window col offsets 2..5 of the center row).
    float c0, c1, c2, c3;
    {
        const float4 a = *(const float4*)&tile[ry + 2][cx];
        const float4 q = *(const float4*)&tile[ry + 2][cx + 4];
        c0 = a.z; c1 = a.w; c2 = q.x; c3 = q.y;
    }

    const int y = ty0 + ry;
    float* __restrict__ p =
        out + ((size_t)b * KCH) * (size_t)(H * W) + (size_t)y * W + (tx0 + cx);

    // Stream the window one row at a time: row i is consumed entirely by the
    // 5 (or 4) channels of kernel-row i, so only 8 row floats + 4 centers
    // stay live -> much lower register pressure than a preloaded 5x8 window.
    #pragma unroll
    for (int i = 0; i < 5; i++) {
        float r[8];
        {
            const float4 a = *(const float4*)&tile[ry + i][cx];
            const float4 q = *(const float4*)&tile[ry + i][cx + 4];
            r[0] = a.x; r[1] = a.y; r[2] = a.z; r[3] = a.w;
            r[4] = q.x; r[5] = q.y; r[6] = q.z; r[7] = q.w;
        }
        #pragma unroll
        for (int j = 0; j < 5; j++) {
            if (i == 2 && j == 2) continue;   // center channel skipped
            float4 v;
            v.x = c0 - r[j];
            v.y = c1 - r[j + 1];
            v.z = c2 - r[j + 2];
            v.w = c3 - r[j + 3];
            __stcs((float4*)p, v);            // streaming: write-once output
            p += (size_t)H * W;
        }
    }
}

extern "C" void kernel_launch(void* const* d_in, const int* in_sizes, int n_in,
                              void* d_out, int out_size) {
    const float* x = (const float*)d_in[0];
    float* out = (float*)d_out;

    dim3 block(32, 8, 1);
    dim3 grid(W / TILE_W, H / TILE_H, NB);   // (4, 64, 16)
    local_variation_kernel<<<grid, block>>>(x, out);
}